// round 5
// baseline (speedup 1.0000x reference)
#include <cuda_runtime.h>
#include <math.h>

#define Bb 32
#define Tt 64
#define Ee 512
#define Hh 1024
#define VTv 32000
#define HB (Hh*Bb)          // 32768
#define G4 (4*Hh)           // 4096
#define NBLK 128
#define NTHR 512

typedef unsigned long long u64;

__device__ __forceinline__ u64 pk2(float x, float y) {
    u64 r; asm("mov.b64 %0,{%1,%2};" : "=l"(r) : "f"(x), "f"(y)); return r;
}
__device__ __forceinline__ void fma2(u64 &d, u64 a, u64 b) {
    asm("fma.rn.f32x2 %0,%1,%2,%0;" : "+l"(d) : "l"(a), "l"(b));
}
__device__ __forceinline__ float2 up2(u64 v) {
    float2 f; asm("mov.b64 {%0,%1},%2;" : "=f"(f.x), "=f"(f.y) : "l"(v)); return f;
}
__device__ __forceinline__ float sigf(float x) { return 1.f/(1.f+expf(-x)); }

// ---------------- scratch ----------------
__device__ __align__(16) float g_srcX[Tt*HB];   // phase0: x-proj; phase1: h0e chain
__device__ __align__(16) float g_tgtX[Tt*HB];   // phase0: x-proj; phase1: h0d chain
__device__ __align__(16) float g_encHs[Tt*HB];
__device__ __align__(16) float g_h1d[2*HB];
__device__ __align__(16) float g_c0e[HB];
__device__ __align__(16) float g_c1e[HB];
__device__ __align__(16) float g_c0d[HB];
__device__ __align__(16) float g_c1d[HB];
__device__ __align__(16) float g_zero[HB];
__device__ __align__(16) float g_scoresT[Tt*Bb];
__device__ __align__(16) float g_ctxT[HB];
__device__ __align__(16) float g_wcPart[6*HB];
__device__ __align__(16) float g_htT[HB];
__device__ __align__(16) float g_oePart[8*Ee*Bb];
__device__ __align__(16) float g_outemb[Tt*Bb*Ee];     // [2048][512]
__device__ __align__(16) float g_Wre[2*2*Hh*G4];
__device__ __align__(16) float g_Wrd[2*2*Hh*G4];
__device__ __align__(16) float g_bre[2*G4];
__device__ __align__(16) float g_brd[2*G4];
__device__ __align__(16) float g_zxe[Tt*G4*Bb];
__device__ __align__(16) float g_zxd[Tt*G4*Bb];
__device__ __align__(16) float g_elog[(size_t)Tt*Bb*VTv];
__device__ unsigned g_bar;

// dynamic smem:
//  As : u64  [2][128][32]   0      .. 65536
//  Ws : float[2][128][32]   65536  .. 98304
//  red: float[8*32*33]      98304  .. 132096
//  attw:float[64*33]        132096 .. 140544
#define SMEM_SEQ 140544
#define SMEM_XG  132096

// ---------------- init ----------------
__global__ void zero_state() {
    int i = blockIdx.x*blockDim.x + threadIdx.x;
    if (i == 0) g_bar = 0u;
    if (i < HB) {
        g_zero[i]=0.f; g_c0e[i]=0.f; g_c1e[i]=0.f; g_c0d[i]=0.f; g_c1d[i]=0.f;
        g_h1d[i]=0.f; g_h1d[i+HB]=0.f;
    }
}

// W[l][2048][4096] cols g*1024+n  ->  Wr[l][2048][n*4+g]
__global__ void reorder_W(const float* __restrict__ W, const float* __restrict__ b,
                          float* __restrict__ Wr, float* __restrict__ br) {
    long total = 2L*2*Hh*G4;
    for (long i = (long)blockIdx.x*blockDim.x + threadIdx.x; i < total;
         i += (long)gridDim.x*blockDim.x) {
        long row = i >> 12;
        int col = (int)(i & 4095);
        int n = col >> 2, g = col & 3;
        Wr[i] = W[(row<<12) + g*Hh + n];
    }
    int id = blockIdx.x*blockDim.x + threadIdx.x;
    if (id < 2*G4) {
        int l = id >> 12, col = id & 4095, n = col>>2, g = col&3;
        br[id] = b[(l<<12) + g*Hh + n];
    }
}

// ---------------- embedding + input projection ----------------
__global__ void embed_proj(const int* __restrict__ tok,
                           const float* __restrict__ emb,
                           const float4* __restrict__ W4,
                           const float4* __restrict__ b4,
                           float* __restrict__ outX) {
    int t = blockIdx.y;
    int w = threadIdx.x >> 5, lane = threadIdx.x & 31;
    int n4 = blockIdx.x * 8 + w;
    const float* ar = emb + (long)tok[lane*Tt + t] * Ee;
    float4 acc = b4[n4];
    #pragma unroll 4
    for (int k = 0; k < Ee; k++) {
        float a = ar[k];
        float4 wv = W4[k*(Hh/4) + n4];
        acc.x += a*wv.x; acc.y += a*wv.y; acc.z += a*wv.z; acc.w += a*wv.w;
    }
    float* o = outX + (long)t*HB + (n4*4)*Bb + lane;
    o[0]=acc.x; o[32]=acc.y; o[64]=acc.z; o[96]=acc.w;
}

// ---------------- 512-thread double-buffered tile GEMM ----------------
// 16 warps = 2 colgroups (16 cols) x 8 in-tile ksplits (16 k each).
// Accumulates into red[8][32][33]: red[ks][col][b].
// X[k][b] = XA for k<K1 else XB[k-K1]; W row-major [k][ldw].
__device__ __forceinline__ void stage_mm(
    const float* __restrict__ XA, const float* __restrict__ XB, int K1,
    int kbeg, int kend, const float* __restrict__ W, int ldw, int ncol0,
    u64* As, float* Ws, float* red)
{
    int tid = threadIdx.x, lane = tid & 31, wid = tid >> 5;
    int cg = wid >> 3, ks = wid & 7;
    int r0 = tid >> 2, c8 = (tid & 3) * 8;
    u64 acc[8] = {};
    int nt = (kend - kbeg) >> 7;
    float4 pa0, pa1, pw0, pw1;
    {
        int ka = kbeg + r0;
        const float* Xp = (ka < K1) ? XA + (long)ka*Bb : XB + (long)(ka-K1)*Bb;
        pa0 = *(const float4*)(Xp + c8);
        pa1 = *(const float4*)(Xp + c8 + 4);
        const float* Wp = W + (long)ka*ldw + ncol0 + c8;
        pw0 = *(const float4*)(Wp);
        pw1 = *(const float4*)(Wp + 4);
    }
    for (int it = 0; it < nt; it++) {
        u64* Ab = As + (it & 1)*(128*32);
        float* Wb = Ws + (it & 1)*(128*32);
        {
            u64* A0 = Ab + r0*32 + c8;
            A0[0]=pk2(pa0.x,pa0.x); A0[1]=pk2(pa0.y,pa0.y);
            A0[2]=pk2(pa0.z,pa0.z); A0[3]=pk2(pa0.w,pa0.w);
            A0[4]=pk2(pa1.x,pa1.x); A0[5]=pk2(pa1.y,pa1.y);
            A0[6]=pk2(pa1.z,pa1.z); A0[7]=pk2(pa1.w,pa1.w);
            float* W0 = Wb + r0*32 + c8;
            *(float4*)W0 = pw0;
            *(float4*)(W0+4) = pw1;
        }
        __syncthreads();
        if (it + 1 < nt) {
            int ka = kbeg + (it+1)*128 + r0;
            const float* Xp = (ka < K1) ? XA + (long)ka*Bb : XB + (long)(ka-K1)*Bb;
            pa0 = *(const float4*)(Xp + c8);
            pa1 = *(const float4*)(Xp + c8 + 4);
            const float* Wp = W + (long)ka*ldw + ncol0 + c8;
            pw0 = *(const float4*)(Wp);
            pw1 = *(const float4*)(Wp + 4);
        }
        const u64* Ar = Ab + (ks*16)*32 + lane;
        const float* Wr = Wb + (ks*16)*32 + cg*16;
        #pragma unroll
        for (int kk = 0; kk < 16; kk++) {
            u64 aa = Ar[kk*32];
            const ulonglong2* wq = (const ulonglong2*)(Wr + kk*32);
            ulonglong2 w0 = wq[0], w1 = wq[1], w2 = wq[2], w3 = wq[3];
            fma2(acc[0], aa, w0.x); fma2(acc[1], aa, w0.y);
            fma2(acc[2], aa, w1.x); fma2(acc[3], aa, w1.y);
            fma2(acc[4], aa, w2.x); fma2(acc[5], aa, w2.y);
            fma2(acc[6], aa, w3.x); fma2(acc[7], aa, w3.y);
        }
        __syncthreads();
    }
    #pragma unroll
    for (int a = 0; a < 8; a++) {
        float2 v = up2(acc[a]);
        red[(ks*32 + cg*16 + 2*a)*33 + lane]     = v.x;
        red[(ks*32 + cg*16 + 2*a + 1)*33 + lane] = v.y;
    }
    __syncthreads();
}

// reduce 8 ksplits + LSTM cell; block covers n = bid*8..+8
__device__ __forceinline__ void lstm_epi(const float* red, const float* __restrict__ b4,
                                         const float* __restrict__ zx,
                                         float* __restrict__ c, float* __restrict__ h,
                                         int bid) {
    int tid = threadIdx.x, lane = tid & 31, w = tid >> 5;
    if (w < 8) {
        int n = bid*8 + w;
        float zi=0.f, zj=0.f, zf=0.f, zo=0.f;
        #pragma unroll
        for (int s = 0; s < 8; s++) {
            const float* r = red + (s*32 + w*4)*33 + lane;
            zi += r[0]; zj += r[33]; zf += r[66]; zo += r[99];
        }
        const float* bb = b4 + n*4;
        zi += bb[0]; zj += bb[1]; zf += bb[2]; zo += bb[3];
        if (zx) {
            const float* z = zx + n*128 + lane;
            zi += z[0]; zj += z[32]; zf += z[64]; zo += z[96];
        }
        int idx = n*Bb + lane;
        float cn = c[idx]*sigf(zf + 1.f) + sigf(zi)*tanhf(zj);
        c[idx] = cn;
        h[idx] = tanhf(cn)*sigf(zo);
    }
    __syncthreads();
}

// reduce 8 ksplits -> dst[c*32+b]
__device__ __forceinline__ void part_epi(const float* red, float* __restrict__ dst) {
    for (int i = threadIdx.x; i < 32*32; i += NTHR) {
        int cl = i >> 5, b = i & 31;
        float s = 0.f;
        #pragma unroll
        for (int sl = 0; sl < 8; sl++) s += red[(sl*32 + cl)*33 + b];
        dst[cl*32 + b] = s;
    }
}

// ---------------- xgate precompute ----------------
__global__ void __launch_bounds__(NTHR) xgate(const float* __restrict__ X,
                                              const float* __restrict__ W,
                                              float* __restrict__ out) {
    extern __shared__ __align__(16) unsigned char dynsmem[];
    u64* As = (u64*)dynsmem;
    float* Ws = (float*)(dynsmem + 65536);
    float* red = (float*)(dynsmem + 98304);
    int t = blockIdx.y, ncol0 = blockIdx.x * 32;
    stage_mm(X + (long)t*HB, X, 1<<30, 0, 1024, W, 4096, ncol0, As, Ws, red);
    part_epi(red, out + (long)t*(G4*Bb) + ncol0*32);
}

// ---------------- grid barrier ----------------
__device__ __forceinline__ void gbar(unsigned &tgt) {
    tgt += NBLK;
    __syncthreads();
    if (threadIdx.x == 0) {
        __threadfence();
        atomicAdd(&g_bar, 1u);
        unsigned v;
        do {
            asm volatile("ld.acquire.gpu.u32 %0,[%1];" : "=r"(v) : "l"(&g_bar) : "memory");
        } while (v < tgt);
    }
    __syncthreads();
}

// ---------------- persistent sequence kernel ----------------
__global__ void __launch_bounds__(NTHR,1) seq_kernel(const float* __restrict__ W_c,
                                                     const float* __restrict__ b_c,
                                                     const float* __restrict__ proj_W,
                                                     const float* __restrict__ proj_b) {
    extern __shared__ __align__(16) unsigned char dynsmem[];
    u64* As = (u64*)dynsmem;
    float* Ws = (float*)(dynsmem + 65536);
    float* red = (float*)(dynsmem + 98304);
    float* attw = (float*)(dynsmem + 132096);   // [64][33]
    int tid = threadIdx.x, lane = tid & 31, wid = tid >> 5, bid = blockIdx.x;
    unsigned tgt = 0;

    const float* We0h = g_Wre + (long)1024*4096;
    const float* We1  = g_Wre + (long)2048*4096;
    const float* Wd0h = g_Wrd + (long)1024*4096;
    const float* Wd1  = g_Wrd + (long)2048*4096;
    const float* be0 = g_bre;
    const float* be1 = g_bre + G4;
    const float* bd0 = g_brd;
    const float* bd1 = g_brd + G4;
    int ncol0 = bid * 32;

    // ---- phase 1: encoder (both layers) + decoder layer0 ----
    for (int t = 0; t < Tt; t++) {
        const float* h0eprev = t ? (g_srcX + (long)(t-1)*HB) : g_zero;
        const float* h0dprev = t ? (g_tgtX + (long)(t-1)*HB) : g_zero;
        // enc layer0 h-part
        stage_mm(h0eprev, h0eprev, 1<<30, 0, 1024, We0h, 4096, ncol0, As, Ws, red);
        lstm_epi(red, be0, g_zxe + (long)t*(G4*Bb), g_c0e, g_srcX + (long)t*HB, bid);
        // dec layer0 h-part
        stage_mm(h0dprev, h0dprev, 1<<30, 0, 1024, Wd0h, 4096, ncol0, As, Ws, red);
        lstm_epi(red, bd0, g_zxd + (long)t*(G4*Bb), g_c0d, g_tgtX + (long)t*HB, bid);
        gbar(tgt);
        // enc layer1
        const float* h1prev = t ? (g_encHs + (long)(t-1)*HB) : g_zero;
        stage_mm(g_srcX + (long)t*HB, h1prev, 1024, 0, 2048, We1, 4096, ncol0, As, Ws, red);
        lstm_epi(red, be1, nullptr, g_c1e, g_encHs + (long)t*HB, bid);
        gbar(tgt);
    }

    // ---- phase 2: decoder layer1 + attention + projections ----
    for (int t = 0; t < Tt; t++) {
        int p = t & 1;
        const float* h1prev = g_h1d + p*HB;
        float* h1cur = g_h1d + (1-p)*HB;

        // S1: dec layer1
        stage_mm(g_tgtX + (long)t*HB, h1prev, 1024, 0, 2048, Wd1, 4096, ncol0, As, Ws, red);
        lstm_epi(red, bd1, nullptr, g_c1d, h1cur, bid);
        gbar(tgt);

        // S2: scores (blocks 0-63) || W_c h-part (blocks 64-127)
        if (bid < Tt) {
            const float* e = g_encHs + (long)bid*HB;
            float s = 0.f;
            #pragma unroll 4
            for (int hh = wid*64; hh < wid*64 + 64; hh++)
                s += h1cur[hh*Bb + lane] * e[hh*Bb + lane];
            attw[wid*33 + lane] = s;
            __syncthreads();
            if (wid == 0) {
                float a = 0.f;
                #pragma unroll
                for (int j = 0; j < 16; j++) a += attw[j*33 + lane];
                g_scoresT[bid*Bb + lane] = a;
            }
            __syncthreads();
        } else {
            int bb = bid - 64;
            int nc = (bb >> 1) * 32, ksg = bb & 1;
            stage_mm(h1cur, h1cur, 1<<30, ksg*512, ksg*512 + 512, W_c, 1024, nc,
                     As, Ws, red);
            part_epi(red, g_wcPart + (long)ksg*HB + nc*32);
        }
        gbar(tgt);

        // S3: softmax (warp 0, redundant per block) + ctx
        if (wid == 0) {
            float mx = -1e30f;
            #pragma unroll
            for (int q = 0; q < Tt; q++) mx = fmaxf(mx, g_scoresT[q*Bb + lane]);
            float sum = 0.f;
            #pragma unroll
            for (int q = 0; q < Tt; q++) {
                float e = expf(g_scoresT[q*Bb + lane] - mx);
                attw[q*33 + lane] = e; sum += e;
            }
            float inv = 1.f/sum;
            #pragma unroll
            for (int q = 0; q < Tt; q++) attw[q*33 + lane] *= inv;
        }
        __syncthreads();
        if (wid < 8) {
            int hh = bid*8 + wid;
            float s = 0.f;
            #pragma unroll 8
            for (int q = 0; q < Tt; q++)
                s += attw[q*33 + lane] * g_encHs[((long)q*Hh + hh)*Bb + lane];
            g_ctxT[hh*Bb + lane] = s;
        }
        gbar(tgt);

        // S4: W_c ctx-part (32 coltiles x 4 ksplit)
        {
            int nc = (bid >> 2) * 32, ksg = bid & 3;
            stage_mm(g_ctxT, g_ctxT, 1<<30, ksg*256, ksg*256 + 256,
                     W_c + (long)1024*1024, 1024, nc, As, Ws, red);
            part_epi(red, g_wcPart + (long)(2 + ksg)*HB + nc*32);
        }
        gbar(tgt);

        // S5: reduce -> htT
        if (bid < 64) {
            int id = bid*NTHR + tid;
            int n = id >> 5;
            float s = b_c[n];
            #pragma unroll
            for (int sl = 0; sl < 6; sl++) s += g_wcPart[(long)sl*HB + id];
            g_htT[id] = s;
        }
        gbar(tgt);

        // S6: proj (16 coltiles x 8 ksplit)
        {
            int nc = (bid >> 3) * 32, ksg = bid & 7;
            stage_mm(g_htT, g_htT, 1<<30, ksg*128, ksg*128 + 128, proj_W, 512, nc,
                     As, Ws, red);
            part_epi(red, g_oePart + (long)ksg*(Ee*Bb) + nc*32);
        }
        gbar(tgt);

        // S7: reduce -> outemb row-major [t*32+b][512]
        if (bid < 32) {
            int id = bid*NTHR + tid;
            int n = id >> 5, b = id & 31;
            float s = proj_b[n];
            #pragma unroll
            for (int s8 = 0; s8 < 8; s8++) s += g_oePart[(long)s8*(Ee*Bb) + id];
            g_outemb[((long)t*Bb + b)*Ee + n] = s;
        }
        gbar(tgt);
    }
}

// ---------------- vocab GEMM with exp() epilogue ----------------
__global__ void __launch_bounds__(256) gemm_logits(const float* __restrict__ A,
                                                   const float* __restrict__ Bw,
                                                   const float* __restrict__ bias,
                                                   float* __restrict__ E) {
    __shared__ float As[16][64];
    __shared__ float Bs[16][64];
    int tid = threadIdx.x;
    int bn = blockIdx.x * 64;
    int bm = blockIdx.y * 64;
    int tx = tid & 15, ty = tid >> 4;
    int arow = tid >> 2, akq = tid & 3;
    int brow = tid >> 4, bcq = tid & 15;
    u64 acc2[4][2] = {};
    for (int k0 = 0; k0 < 512; k0 += 16) {
        float4 av = *(const float4*)(A + (long)(bm+arow)*Ee + k0 + akq*4);
        As[akq*4+0][arow]=av.x; As[akq*4+1][arow]=av.y;
        As[akq*4+2][arow]=av.z; As[akq*4+3][arow]=av.w;
        float4 bv = *(const float4*)(Bw + (long)(k0+brow)*VTv + bn + bcq*4);
        *(float4*)&Bs[brow][bcq*4] = bv;
        __syncthreads();
        #pragma unroll
        for (int kk = 0; kk < 16; kk++) {
            float4 a4 = *(const float4*)&As[kk][ty*4];
            ulonglong2 b2 = *(const ulonglong2*)&Bs[kk][tx*4];
            u64 aa;
            aa = pk2(a4.x, a4.x); fma2(acc2[0][0], aa, b2.x); fma2(acc2[0][1], aa, b2.y);
            aa = pk2(a4.y, a4.y); fma2(acc2[1][0], aa, b2.x); fma2(acc2[1][1], aa, b2.y);
            aa = pk2(a4.z, a4.z); fma2(acc2[2][0], aa, b2.x); fma2(acc2[2][1], aa, b2.y);
            aa = pk2(a4.w, a4.w); fma2(acc2[3][0], aa, b2.x); fma2(acc2[3][1], aa, b2.y);
        }
        __syncthreads();
    }
    #pragma unroll
    for (int i = 0; i < 4; i++) {
        float* erow = E + (size_t)(bm+ty*4+i)*VTv + bn + tx*4;
        float2 c01 = up2(acc2[i][0]), c23 = up2(acc2[i][1]);
        erow[0] = expf(c01.x + bias[bn+tx*4+0]);
        erow[1] = expf(c01.y + bias[bn+tx*4+1]);
        erow[2] = expf(c23.x + bias[bn+tx*4+2]);
        erow[3] = expf(c23.y + bias[bn+tx*4+3]);
    }
}

// ---------------- normalize + layout remap ----------------
__global__ void softmax_norm(const float* __restrict__ E, float* __restrict__ out) {
    int m = blockIdx.x;                      // m = t*32 + b
    const float* er = E + (size_t)m*VTv;
    int tid = threadIdx.x;
    __shared__ float red[256];
    float sum = 0.f;
    for (int i = tid; i < VTv; i += 256) sum += er[i];
    red[tid] = sum; __syncthreads();
    for (int s = 128; s; s >>= 1) { if (tid < s) red[tid] += red[tid+s]; __syncthreads(); }
    float inv = 1.f/red[0];
    int t = m >> 5, b = m & 31;
    float* orow = out + (size_t)(b*Tt + t)*VTv;
    for (int i = tid; i < VTv; i += 256) orow[i] = er[i]*inv;
}

// ---------------- host ----------------
extern "C" void kernel_launch(void* const* d_in, const int* in_sizes, int n_in,
                              void* d_out, int out_size) {
    const int*   src    = (const int*)d_in[0];
    const int*   tgt    = (const int*)d_in[1];
    const float* s_emb  = (const float*)d_in[2];
    const float* s_pW   = (const float*)d_in[3];
    const float* s_pb   = (const float*)d_in[4];
    const float* t_emb  = (const float*)d_in[5];
    const float* t_pW   = (const float*)d_in[6];
    const float* t_pb   = (const float*)d_in[7];
    const float* enc_W  = (const float*)d_in[8];
    const float* enc_b  = (const float*)d_in[9];
    const float* dec_W  = (const float*)d_in[10];
    const float* dec_b  = (const float*)d_in[11];
    const float* W_c    = (const float*)d_in[12];
    const float* b_c    = (const float*)d_in[13];
    const float* proj_W = (const float*)d_in[14];
    const float* proj_b = (const float*)d_in[15];
    const float* proj_Wo= (const float*)d_in[16];
    const float* proj_bo= (const float*)d_in[17];
    float* out = (float*)d_out;

    float *srcX,*tgtX,*Wre,*Wrd,*bre,*brd,*zxe,*zxd,*outemb,*elog;
    cudaGetSymbolAddress((void**)&srcX,   g_srcX);
    cudaGetSymbolAddress((void**)&tgtX,   g_tgtX);
    cudaGetSymbolAddress((void**)&Wre,    g_Wre);
    cudaGetSymbolAddress((void**)&Wrd,    g_Wrd);
    cudaGetSymbolAddress((void**)&bre,    g_bre);
    cudaGetSymbolAddress((void**)&brd,    g_brd);
    cudaGetSymbolAddress((void**)&zxe,    g_zxe);
    cudaGetSymbolAddress((void**)&zxd,    g_zxd);
    cudaGetSymbolAddress((void**)&outemb, g_outemb);
    cudaGetSymbolAddress((void**)&elog,   g_elog);

    cudaFuncSetAttribute(seq_kernel, cudaFuncAttributeMaxDynamicSharedMemorySize, SMEM_SEQ);
    cudaFuncSetAttribute(xgate,      cudaFuncAttributeMaxDynamicSharedMemorySize, SMEM_XG);

    zero_state<<<(HB+255)/256, 256>>>();
    reorder_W<<<1024, 256>>>(enc_W, enc_b, Wre, bre);
    reorder_W<<<1024, 256>>>(dec_W, dec_b, Wrd, brd);
    embed_proj<<<dim3(32,64), 256>>>(src, s_emb, (const float4*)s_pW, (const float4*)s_pb, srcX);
    embed_proj<<<dim3(32,64), 256>>>(tgt, t_emb, (const float4*)t_pW, (const float4*)t_pb, tgtX);

    // x-part gate pre-activations (layer 0 of each stack), all timesteps
    xgate<<<dim3(128,Tt), NTHR, SMEM_XG>>>(srcX, Wre, zxe);
    xgate<<<dim3(128,Tt), NTHR, SMEM_XG>>>(tgtX, Wrd, zxd);

    // recurrent encoder + decoder in one persistent kernel
    seq_kernel<<<NBLK, NTHR, SMEM_SEQ>>>(W_c, b_c, proj_W, proj_b);

    // vocab projection (+exp) and normalization
    gemm_logits<<<dim3(VTv/64, (Tt*Bb)/64), 256>>>(outemb, proj_Wo, proj_bo, elog);
    softmax_norm<<<Tt*Bb, 256>>>(elog, out);
}

// round 6
// speedup vs baseline: 1.3746x; 1.3746x over previous
#include <cuda_runtime.h>
#include <math.h>
#include <stdint.h>

#define Bb 32
#define Tt 64
#define Ee 512
#define Hh 1024
#define VTv 32000
#define HB (Hh*Bb)          // 32768
#define G4 (4*Hh)           // 4096
#define NBLK 128
#define NTHR 512

typedef unsigned long long u64;

__device__ __forceinline__ u64 pk2(float x, float y) {
    u64 r; asm("mov.b64 %0,{%1,%2};" : "=l"(r) : "f"(x), "f"(y)); return r;
}
__device__ __forceinline__ void fma2(u64 &d, u64 a, u64 b) {
    asm("fma.rn.f32x2 %0,%1,%2,%0;" : "+l"(d) : "l"(a), "l"(b));
}
__device__ __forceinline__ float2 up2(u64 v) {
    float2 f; asm("mov.b64 {%0,%1},%2;" : "=f"(f.x), "=f"(f.y) : "l"(v)); return f;
}
__device__ __forceinline__ float sigf(float x) { return 1.f/(1.f+expf(-x)); }

__device__ __forceinline__ uint32_t s2u(const void* p) {
    uint32_t a;
    asm("{ .reg .u64 t; cvta.to.shared.u64 t, %1; cvt.u32.u64 %0, t; }" : "=r"(a) : "l"(p));
    return a;
}
__device__ __forceinline__ void mb_init(uint32_t mbar, uint32_t cnt) {
    asm volatile("mbarrier.init.shared.b64 [%0], %1;" :: "r"(mbar), "r"(cnt) : "memory");
}
__device__ __forceinline__ void mb_expect(uint32_t mbar, uint32_t bytes) {
    asm volatile("mbarrier.arrive.expect_tx.shared.b64 _, [%0], %1;" :: "r"(mbar), "r"(bytes) : "memory");
}
__device__ __forceinline__ void mb_wait(uint32_t mbar, int parity) {
    uint32_t done;
    do {
        asm volatile(
            "{\n\t.reg .pred p;\n\t"
            "mbarrier.try_wait.parity.acquire.cta.shared::cta.b64 p, [%1], %2;\n\t"
            "selp.b32 %0,1,0,p;\n\t}"
            : "=r"(done) : "r"(mbar), "r"((uint32_t)parity) : "memory");
    } while (!done);
}
__device__ __forceinline__ void bulk_g2s(uint32_t dst, const void* src, uint32_t bytes, uint32_t mbar) {
    asm volatile(
        "cp.async.bulk.shared::cluster.global.mbarrier::complete_tx::bytes [%0], [%1], %2, [%3];"
        :: "r"(dst), "l"(src), "r"(bytes), "r"(mbar) : "memory");
}

// ---------------- scratch ----------------
__device__ __align__(16) float g_srcX[Tt*HB];   // phase0: x-proj; phase1: h0e chain
__device__ __align__(16) float g_tgtX[Tt*HB];   // phase0: x-proj; phase1: h0d chain
__device__ __align__(16) float g_encHs[Tt*HB];
__device__ __align__(16) float g_h1d[2*HB];
__device__ __align__(16) float g_c0e[HB];
__device__ __align__(16) float g_c1e[HB];
__device__ __align__(16) float g_c0d[HB];
__device__ __align__(16) float g_c1d[HB];
__device__ __align__(16) float g_zero[HB];
__device__ __align__(16) float g_scoresT[Tt*Bb];
__device__ __align__(16) float g_ctxT[HB];
__device__ __align__(16) float g_wcPart[6*HB];
__device__ __align__(16) float g_htT[HB];
__device__ __align__(16) float g_oePart[8*Ee*Bb];
__device__ __align__(16) float g_outembT[Ee*Tt*Bb];   // TRANSPOSED [512][2048]
__device__ __align__(16) float g_Wre[2*2*Hh*G4];      // tiled [l][128ct][2048k][32c]
__device__ __align__(16) float g_Wrd[2*2*Hh*G4];
__device__ __align__(16) float g_Wct[32*2*Hh*32];     // W_c tiled [32ct][2048k][32c]
__device__ __align__(16) float g_pjt[16*Hh*32];       // proj_W tiled [16ct][1024k][32c]
__device__ __align__(16) float g_bre[2*G4];
__device__ __align__(16) float g_brd[2*G4];
__device__ __align__(16) float g_zxe[Tt*G4*Bb];
__device__ __align__(16) float g_zxd[Tt*G4*Bb];
__device__ __align__(16) float g_elog[(size_t)Tt*Bb*VTv];
__device__ unsigned g_bar;

// dynamic smem layout:
//  Af[2][4096]f : 0..32768      (buf0 0..16384, buf1 16384..32768)
//  Wf[2][4096]f : 32768..65536
//  red[8*32*33] : 65536..99328
//  attw[64*33]  : 99328..107776
//  mbar u64[2]  : 107776..107792
#define AF_OFF   0
#define WF_OFF   32768
#define RED_OFF  65536
#define ATT_OFF  99328
#define MBAR_OFF 107776
#define SMEM_TOT 107792

// ---------------- init ----------------
__global__ void zero_state() {
    int i = blockIdx.x*blockDim.x + threadIdx.x;
    if (i == 0) g_bar = 0u;
    if (i < HB) {
        g_zero[i]=0.f; g_c0e[i]=0.f; g_c1e[i]=0.f; g_c0d[i]=0.f; g_c1d[i]=0.f;
        g_h1d[i]=0.f; g_h1d[i+HB]=0.f;
    }
}

// LSTM weights: W[l][2048][4096] (cols g*1024+n) -> tiled [l][128ct][2048k][32c], gate-interleaved
__global__ void tile_lstm_W(const float* __restrict__ W, const float* __restrict__ b,
                            float* __restrict__ dst, float* __restrict__ br) {
    long total = 2L*2048*4096;
    for (long i = (long)blockIdx.x*blockDim.x + threadIdx.x; i < total;
         i += (long)gridDim.x*blockDim.x) {
        int c = (int)(i & 31);
        long r = i >> 5;
        int k = (int)(r & 2047); r >>= 11;
        int ct = (int)(r & 127);
        int l = (int)(r >> 7);
        int col = ct*32 + c;
        int n = col >> 2, g = col & 3;
        dst[i] = W[((long)(l*2048 + k))*4096 + g*1024 + n];
    }
    int id = blockIdx.x*blockDim.x + threadIdx.x;
    if (id < 2*G4) {
        int l = id >> 12, col = id & 4095, n = col>>2, g = col&3;
        br[id] = b[(l<<12) + g*Hh + n];
    }
}

// plain tiling: src[K][N] -> dst[N/32 ct][K][32]
__global__ void tile_plain(const float* __restrict__ src, float* __restrict__ dst,
                           int K, int N) {
    long total = (long)K*N;
    for (long i = (long)blockIdx.x*blockDim.x + threadIdx.x; i < total;
         i += (long)gridDim.x*blockDim.x) {
        int c = (int)(i & 31);
        long r = i >> 5;
        int k = (int)(r % K);
        int ct = (int)(r / K);
        dst[i] = src[(long)k*N + ct*32 + c];
    }
}

// ---------------- embedding + input projection ----------------
__global__ void embed_proj(const int* __restrict__ tok,
                           const float* __restrict__ emb,
                           const float4* __restrict__ W4,
                           const float4* __restrict__ b4,
                           float* __restrict__ outX) {
    int t = blockIdx.y;
    int w = threadIdx.x >> 5, lane = threadIdx.x & 31;
    int n4 = blockIdx.x * 8 + w;
    const float* ar = emb + (long)tok[lane*Tt + t] * Ee;
    float4 acc = b4[n4];
    #pragma unroll 4
    for (int k = 0; k < Ee; k++) {
        float a = ar[k];
        float4 wv = W4[k*(Hh/4) + n4];
        acc.x += a*wv.x; acc.y += a*wv.y; acc.z += a*wv.z; acc.w += a*wv.w;
    }
    float* o = outX + (long)t*HB + (n4*4)*Bb + lane;
    o[0]=acc.x; o[32]=acc.y; o[64]=acc.z; o[96]=acc.w;
}

// ---------------- TMA-staged tile GEMM ----------------
// 512 thr = 16 warps = 2 colgroups x 8 ksplit. red[8][32][33] partials.
// A[k][b]: XA for k<K1 else XB. Wt = coltile base, row stride 32 floats.
__device__ __forceinline__ void stage_tma(
    const float* __restrict__ XA, const float* __restrict__ XB, int K1,
    int kbeg, int kend, const float* __restrict__ Wt,
    char* sm, uint32_t smb, int &ph0, int &ph1, float* red)
{
    int tid = threadIdx.x, lane = tid & 31, wid = tid >> 5;
    int cg = wid >> 3, ks = wid & 7;
    int nt = (kend - kbeg) >> 7;
    uint32_t mb0 = smb + MBAR_OFF, mb1 = smb + MBAR_OFF + 8;
    u64 acc[8] = {};
    if (tid == 0) {
        int kr = kbeg;
        const float* As0 = (kr < K1) ? XA + (long)kr*32 : XB + (long)(kr-K1)*32;
        mb_expect(mb0, 32768);
        bulk_g2s(smb + AF_OFF, As0, 16384, mb0);
        bulk_g2s(smb + WF_OFF, Wt + (long)kr*32, 16384, mb0);
    }
    for (int it = 0; it < nt; it++) {
        int buf = it & 1;
        if (it + 1 < nt && tid == 0) {
            int kr = kbeg + (it+1)*128;
            const float* Asn = (kr < K1) ? XA + (long)kr*32 : XB + (long)(kr-K1)*32;
            uint32_t mbn = (buf ^ 1) ? mb1 : mb0;
            mb_expect(mbn, 32768);
            bulk_g2s(smb + AF_OFF + (buf^1)*16384, Asn, 16384, mbn);
            bulk_g2s(smb + WF_OFF + (buf^1)*16384, Wt + (long)kr*32, 16384, mbn);
        }
        if (buf) { mb_wait(mb1, ph1); ph1 ^= 1; }
        else     { mb_wait(mb0, ph0); ph0 ^= 1; }
        const float* Ab = (const float*)(sm + AF_OFF + buf*16384);
        const float* Wb = (const float*)(sm + WF_OFF + buf*16384);
        const float* Ar = Ab + (ks*16)*32;
        const float* Wr = Wb + (ks*16)*32 + cg*16;
        #pragma unroll
        for (int kk = 0; kk < 16; kk++) {
            float a = Ar[kk*32 + lane];
            u64 aa = pk2(a, a);
            const ulonglong2* wq = (const ulonglong2*)(Wr + kk*32);
            ulonglong2 w0 = wq[0], w1 = wq[1], w2 = wq[2], w3 = wq[3];
            fma2(acc[0], aa, w0.x); fma2(acc[1], aa, w0.y);
            fma2(acc[2], aa, w1.x); fma2(acc[3], aa, w1.y);
            fma2(acc[4], aa, w2.x); fma2(acc[5], aa, w2.y);
            fma2(acc[6], aa, w3.x); fma2(acc[7], aa, w3.y);
        }
        __syncthreads();
    }
    #pragma unroll
    for (int a = 0; a < 8; a++) {
        float2 v = up2(acc[a]);
        red[(ks*32 + cg*16 + 2*a)*33 + lane]     = v.x;
        red[(ks*32 + cg*16 + 2*a + 1)*33 + lane] = v.y;
    }
    __syncthreads();
}

// reduce 8 ksplits + LSTM cell; block covers n = bid*8..+8
__device__ __forceinline__ void lstm_epi(const float* red, const float* __restrict__ b4,
                                         const float* __restrict__ zx,
                                         float* __restrict__ c, float* __restrict__ h,
                                         int bid) {
    int tid = threadIdx.x, lane = tid & 31, w = tid >> 5;
    if (w < 8) {
        int n = bid*8 + w;
        float zi=0.f, zj=0.f, zf=0.f, zo=0.f;
        #pragma unroll
        for (int s = 0; s < 8; s++) {
            const float* r = red + (s*32 + w*4)*33 + lane;
            zi += r[0]; zj += r[33]; zf += r[66]; zo += r[99];
        }
        const float* bb = b4 + n*4;
        zi += bb[0]; zj += bb[1]; zf += bb[2]; zo += bb[3];
        if (zx) {
            const float* z = zx + n*128 + lane;
            zi += z[0]; zj += z[32]; zf += z[64]; zo += z[96];
        }
        int idx = n*Bb + lane;
        float cn = c[idx]*sigf(zf + 1.f) + sigf(zi)*tanhf(zj);
        c[idx] = cn;
        h[idx] = tanhf(cn)*sigf(zo);
    }
    __syncthreads();
}

// reduce 8 ksplits -> dst[c*32+b]
__device__ __forceinline__ void part_epi(const float* red, float* __restrict__ dst) {
    for (int i = threadIdx.x; i < 32*32; i += NTHR) {
        int cl = i >> 5, b = i & 31;
        float s = 0.f;
        #pragma unroll
        for (int sl = 0; sl < 8; sl++) s += red[(sl*32 + cl)*33 + b];
        dst[cl*32 + b] = s;
    }
}

// ---------------- xgate precompute ----------------
__global__ void __launch_bounds__(NTHR) xgate(const float* __restrict__ X,
                                              const float* __restrict__ Wtiled,
                                              float* __restrict__ out) {
    extern __shared__ __align__(16) char dynsmem[];
    uint32_t smb = s2u(dynsmem);
    float* red = (float*)(dynsmem + RED_OFF);
    int t = blockIdx.y, ct = blockIdx.x;
    if (threadIdx.x == 0) {
        mb_init(smb + MBAR_OFF, 1);
        mb_init(smb + MBAR_OFF + 8, 1);
        asm volatile("fence.proxy.async.shared::cta;" ::: "memory");
    }
    __syncthreads();
    int ph0 = 0, ph1 = 0;
    const float* Wt = Wtiled + (long)ct*2048*32;   // x-part rows 0..1023
    stage_tma(X + (long)t*HB, X, 1<<30, 0, 1024, Wt, dynsmem, smb, ph0, ph1, red);
    part_epi(red, out + (long)t*(G4*Bb) + ct*1024);
}

// ---------------- grid barrier ----------------
__device__ __forceinline__ void gbar(unsigned &tgt) {
    tgt += NBLK;
    __syncthreads();
    if (threadIdx.x == 0) {
        __threadfence();
        atomicAdd(&g_bar, 1u);
        unsigned v;
        do {
            asm volatile("ld.acquire.gpu.u32 %0,[%1];" : "=r"(v) : "l"(&g_bar) : "memory");
        } while (v < tgt);
    }
    __syncthreads();
}

// ---------------- persistent sequence kernel ----------------
__global__ void __launch_bounds__(NTHR,1) seq_kernel(const float* __restrict__ b_c,
                                                     const float* __restrict__ proj_b) {
    extern __shared__ __align__(16) char dynsmem[];
    uint32_t smb = s2u(dynsmem);
    float* red = (float*)(dynsmem + RED_OFF);
    float* attw = (float*)(dynsmem + ATT_OFF);   // [64][33]
    int tid = threadIdx.x, lane = tid & 31, wid = tid >> 5, bid = blockIdx.x;
    unsigned tgt = 0;
    if (tid == 0) {
        mb_init(smb + MBAR_OFF, 1);
        mb_init(smb + MBAR_OFF + 8, 1);
        asm volatile("fence.proxy.async.shared::cta;" ::: "memory");
    }
    __syncthreads();
    int ph0 = 0, ph1 = 0;

    const float* We0h = g_Wre + ((long)bid*2048 + 1024)*32;
    const float* We1  = g_Wre + ((long)(128 + bid)*2048)*32;
    const float* Wd0h = g_Wrd + ((long)bid*2048 + 1024)*32;
    const float* Wd1  = g_Wrd + ((long)(128 + bid)*2048)*32;
    const float* be0 = g_bre;
    const float* be1 = g_bre + G4;
    const float* bd0 = g_brd;
    const float* bd1 = g_brd + G4;

    // ---- phase 1: encoder (both layers) + decoder layer0 ----
    for (int t = 0; t < Tt; t++) {
        const float* h0eprev = t ? (g_srcX + (long)(t-1)*HB) : g_zero;
        const float* h0dprev = t ? (g_tgtX + (long)(t-1)*HB) : g_zero;
        stage_tma(h0eprev, h0eprev, 1<<30, 0, 1024, We0h, dynsmem, smb, ph0, ph1, red);
        lstm_epi(red, be0, g_zxe + (long)t*(G4*Bb), g_c0e, g_srcX + (long)t*HB, bid);
        stage_tma(h0dprev, h0dprev, 1<<30, 0, 1024, Wd0h, dynsmem, smb, ph0, ph1, red);
        lstm_epi(red, bd0, g_zxd + (long)t*(G4*Bb), g_c0d, g_tgtX + (long)t*HB, bid);
        gbar(tgt);
        const float* h1prev = t ? (g_encHs + (long)(t-1)*HB) : g_zero;
        stage_tma(g_srcX + (long)t*HB, h1prev, 1024, 0, 2048, We1, dynsmem, smb, ph0, ph1, red);
        lstm_epi(red, be1, nullptr, g_c1e, g_encHs + (long)t*HB, bid);
        gbar(tgt);
    }

    // ---- phase 2: decoder layer1 + attention + projections ----
    for (int t = 0; t < Tt; t++) {
        int p = t & 1;
        const float* h1prev = g_h1d + p*HB;
        float* h1cur = g_h1d + (1-p)*HB;

        // S1: dec layer1
        stage_tma(g_tgtX + (long)t*HB, h1prev, 1024, 0, 2048, Wd1, dynsmem, smb, ph0, ph1, red);
        lstm_epi(red, bd1, nullptr, g_c1d, h1cur, bid);
        gbar(tgt);

        // S2: scores (blocks 0-63) || W_c h-part (blocks 64-127)
        if (bid < Tt) {
            const float* e = g_encHs + (long)bid*HB;
            float s = 0.f;
            #pragma unroll 4
            for (int hh = wid*64; hh < wid*64 + 64; hh++)
                s += h1cur[hh*Bb + lane] * e[hh*Bb + lane];
            attw[wid*33 + lane] = s;
            __syncthreads();
            if (wid == 0) {
                float a = 0.f;
                #pragma unroll
                for (int j = 0; j < 16; j++) a += attw[j*33 + lane];
                g_scoresT[bid*Bb + lane] = a;
            }
            __syncthreads();
        } else {
            int bb = bid - 64;
            int ct = bb >> 1, ksg = bb & 1;
            stage_tma(h1cur, h1cur, 1<<30, ksg*512, ksg*512 + 512,
                      g_Wct + (long)ct*2048*32, dynsmem, smb, ph0, ph1, red);
            part_epi(red, g_wcPart + (long)ksg*HB + ct*1024);
        }
        gbar(tgt);

        // S3: softmax (warp 0, redundant per block) + ctx
        if (wid == 0) {
            float mx = -1e30f;
            #pragma unroll
            for (int q = 0; q < Tt; q++) mx = fmaxf(mx, g_scoresT[q*Bb + lane]);
            float sum = 0.f;
            #pragma unroll
            for (int q = 0; q < Tt; q++) {
                float e = expf(g_scoresT[q*Bb + lane] - mx);
                attw[q*33 + lane] = e; sum += e;
            }
            float inv = 1.f/sum;
            #pragma unroll
            for (int q = 0; q < Tt; q++) attw[q*33 + lane] *= inv;
        }
        __syncthreads();
        if (wid < 8) {
            int hh = bid*8 + wid;
            float s = 0.f;
            #pragma unroll 8
            for (int q = 0; q < Tt; q++)
                s += attw[q*33 + lane] * g_encHs[((long)q*Hh + hh)*Bb + lane];
            g_ctxT[hh*Bb + lane] = s;
        }
        gbar(tgt);

        // S4: W_c ctx-part (32 coltiles x 4 ksplit, rows 1024.. of W_c)
        {
            int ct = bid >> 2, ksg = bid & 3;
            stage_tma(g_ctxT, g_ctxT, 1<<30, ksg*256, ksg*256 + 256,
                      g_Wct + (long)ct*2048*32 + 1024*32, dynsmem, smb, ph0, ph1, red);
            part_epi(red, g_wcPart + (long)(2 + ksg)*HB + ct*1024);
        }
        gbar(tgt);

        // S5: reduce -> htT
        if (bid < 64) {
            int id = bid*NTHR + tid;
            int n = id >> 5;
            float s = b_c[n];
            #pragma unroll
            for (int sl = 0; sl < 6; sl++) s += g_wcPart[(long)sl*HB + id];
            g_htT[id] = s;
        }
        gbar(tgt);

        // S6: proj (16 coltiles x 8 ksplit)
        {
            int ct = bid >> 3, ksg = bid & 7;
            stage_tma(g_htT, g_htT, 1<<30, ksg*128, ksg*128 + 128,
                      g_pjt + (long)ct*1024*32, dynsmem, smb, ph0, ph1, red);
            part_epi(red, g_oePart + (long)ksg*(Ee*Bb) + ct*1024);
        }
        gbar(tgt);

        // S7: reduce -> outembT [512][2048], col m = t*32+b
        if (bid < 32) {
            int id = bid*NTHR + tid;   // 16384
            int n = id >> 5, b = id & 31;
            float s = proj_b[n];
            #pragma unroll
            for (int s8 = 0; s8 < 8; s8++) s += g_oePart[(long)s8*(Ee*Bb) + id];
            g_outembT[(long)n*2048 + t*Bb + b] = s;
        }
        gbar(tgt);
    }
}

// ---------------- vocab GEMM (128x128 tile, fma-bound) + exp epilogue ----------------
// E[2048][32000] = exp(A^T[512][2048] row-slices @ Bw[512][32000] + bias)
__global__ void __launch_bounds__(512) gemm_logits(const float* __restrict__ AT,
                                                   const float* __restrict__ Bw,
                                                   const float* __restrict__ bias,
                                                   float* __restrict__ E) {
    __shared__ float As[16][128];
    __shared__ float Bs[16][128];
    int tid = threadIdx.x;
    int bn = blockIdx.x * 128;
    int bm = blockIdx.y * 128;
    int r8 = tid >> 5, c32 = tid & 31;
    int sk = tid >> 5, sq = tid & 31;      // staging coords
    u64 acc[8][2] = {};
    float4 pa = *(const float4*)(AT + (long)sk*2048 + bm + sq*4);
    float4 pb = *(const float4*)(Bw + (long)sk*VTv + bn + sq*4);
    for (int k0 = 0; k0 < 512; k0 += 16) {
        *(float4*)&As[sk][sq*4] = pa;
        *(float4*)&Bs[sk][sq*4] = pb;
        __syncthreads();
        if (k0 + 16 < 512) {
            pa = *(const float4*)(AT + (long)(k0+16+sk)*2048 + bm + sq*4);
            pb = *(const float4*)(Bw + (long)(k0+16+sk)*VTv + bn + sq*4);
        }
        #pragma unroll
        for (int k = 0; k < 16; k++) {
            float4 a0 = *(const float4*)&As[k][r8*8];
            float4 a1 = *(const float4*)&As[k][r8*8 + 4];
            float4 bv = *(const float4*)&Bs[k][c32*4];
            u64 b01 = pk2(bv.x, bv.y), b23 = pk2(bv.z, bv.w);
            u64 aa;
            aa = pk2(a0.x,a0.x); fma2(acc[0][0], aa, b01); fma2(acc[0][1], aa, b23);
            aa = pk2(a0.y,a0.y); fma2(acc[1][0], aa, b01); fma2(acc[1][1], aa, b23);
            aa = pk2(a0.z,a0.z); fma2(acc[2][0], aa, b01); fma2(acc[2][1], aa, b23);
            aa = pk2(a0.w,a0.w); fma2(acc[3][0], aa, b01); fma2(acc[3][1], aa, b23);
            aa = pk2(a1.x,a1.x); fma2(acc[4][0], aa, b01); fma2(acc[4][1], aa, b23);
            aa = pk2(a1.y,a1.y); fma2(acc[5][0], aa, b01); fma2(acc[5][1], aa, b23);
            aa = pk2(a1.z,a1.z); fma2(acc[6][0], aa, b01); fma2(acc[6][1], aa, b23);
            aa = pk2(a1.w,a1.w); fma2(acc[7][0], aa, b01); fma2(acc[7][1], aa, b23);
        }
        __syncthreads();
    }
    float4 bi = *(const float4*)(bias + bn + c32*4);
    #pragma unroll
    for (int j = 0; j < 8; j++) {
        float2 v01 = up2(acc[j][0]), v23 = up2(acc[j][1]);
        float4 o;
        o.x = expf(v01.x + bi.x);
        o.y = expf(v01.y + bi.y);
        o.z = expf(v23.x + bi.z);
        o.w = expf(v23.y + bi.w);
        *(float4*)(E + (size_t)(bm + r8*8 + j)*VTv + bn + c32*4) = o;
    }
}

// ---------------- normalize + layout remap ----------------
__global__ void softmax_norm(const float* __restrict__ E, float* __restrict__ out) {
    int m = blockIdx.x;                      // m = t*32 + b
    const float* er = E + (size_t)m*VTv;
    int tid = threadIdx.x;
    __shared__ float red[256];
    float sum = 0.f;
    for (int i = tid; i < VTv; i += 256) sum += er[i];
    red[tid] = sum; __syncthreads();
    for (int s = 128; s; s >>= 1) { if (tid < s) red[tid] += red[tid+s]; __syncthreads(); }
    float inv = 1.f/red[0];
    int t = m >> 5, b = m & 31;
    float* orow = out + (size_t)(b*Tt + t)*VTv;
    for (int i = tid; i < VTv; i += 256) orow[i] = er[i]*inv;
}

// ---------------- host ----------------
extern "C" void kernel_launch(void* const* d_in, const int* in_sizes, int n_in,
                              void* d_out, int out_size) {
    const int*   src    = (const int*)d_in[0];
    const int*   tgt    = (const int*)d_in[1];
    const float* s_emb  = (const float*)d_in[2];
    const float* s_pW   = (const float*)d_in[3];
    const float* s_pb   = (const float*)d_in[4];
    const float* t_emb  = (const float*)d_in[5];
    const float* t_pW   = (const float*)d_in[6];
    const float* t_pb   = (const float*)d_in[7];
    const float* enc_W  = (const float*)d_in[8];
    const float* enc_b  = (const float*)d_in[9];
    const float* dec_W  = (const float*)d_in[10];
    const float* dec_b  = (const float*)d_in[11];
    const float* W_c    = (const float*)d_in[12];
    const float* b_c    = (const float*)d_in[13];
    const float* proj_W = (const float*)d_in[14];
    const float* proj_b = (const float*)d_in[15];
    const float* proj_Wo= (const float*)d_in[16];
    const float* proj_bo= (const float*)d_in[17];
    float* out = (float*)d_out;

    float *srcX,*tgtX,*Wre,*Wrd,*bre,*brd,*Wct,*pjt,*zxe,*zxd,*outembT,*elog;
    cudaGetSymbolAddress((void**)&srcX,    g_srcX);
    cudaGetSymbolAddress((void**)&tgtX,    g_tgtX);
    cudaGetSymbolAddress((void**)&Wre,     g_Wre);
    cudaGetSymbolAddress((void**)&Wrd,     g_Wrd);
    cudaGetSymbolAddress((void**)&bre,     g_bre);
    cudaGetSymbolAddress((void**)&brd,     g_brd);
    cudaGetSymbolAddress((void**)&Wct,     g_Wct);
    cudaGetSymbolAddress((void**)&pjt,     g_pjt);
    cudaGetSymbolAddress((void**)&zxe,     g_zxe);
    cudaGetSymbolAddress((void**)&zxd,     g_zxd);
    cudaGetSymbolAddress((void**)&outembT, g_outembT);
    cudaGetSymbolAddress((void**)&elog,    g_elog);

    cudaFuncSetAttribute(seq_kernel, cudaFuncAttributeMaxDynamicSharedMemorySize, SMEM_TOT);
    cudaFuncSetAttribute(xgate,      cudaFuncAttributeMaxDynamicSharedMemorySize, SMEM_TOT);

    zero_state<<<(HB+255)/256, 256>>>();
    tile_lstm_W<<<4096, 256>>>(enc_W, enc_b, Wre, bre);
    tile_lstm_W<<<4096, 256>>>(dec_W, dec_b, Wrd, brd);
    tile_plain<<<1024, 256>>>(W_c,    Wct, 2048, 1024);
    tile_plain<<<512,  256>>>(proj_W, pjt, 1024, 512);
    embed_proj<<<dim3(32,64), 256>>>(src, s_emb, (const float4*)s_pW, (const float4*)s_pb, srcX);
    embed_proj<<<dim3(32,64), 256>>>(tgt, t_emb, (const float4*)t_pW, (const float4*)t_pb, tgtX);

    // x-part gate pre-activations (layer 0 of each stack), all timesteps
    xgate<<<dim3(128,Tt), NTHR, SMEM_TOT>>>(srcX, Wre, zxe);
    xgate<<<dim3(128,Tt), NTHR, SMEM_TOT>>>(tgtX, Wrd, zxd);

    // recurrent encoder + decoder in one persistent kernel
    seq_kernel<<<NBLK, NTHR, SMEM_TOT>>>(b_c, proj_b);

    // vocab projection (+exp) and normalization
    gemm_logits<<<dim3(VTv/128, (Tt*Bb)/128), 512>>>(outembT, proj_Wo, proj_bo, elog);
    softmax_norm<<<Tt*Bb, 256>>>(elog, out);
}